// round 2
// baseline (speedup 1.0000x reference)
#include <cuda_runtime.h>

// NonMaximaSuppression2d: x (8,32,512,512) fp32.
// m = max over 8 neighbors (replicate pad), floored at 0 (zeroed center tap).
// out = x * (x > m).
// Pure HBM-streaming kernel: float4 along W, 3-row register slide along H.

#define HH 512
#define WW 512
#define RPT 16          // rows per thread strip
#define TPB 128         // threads per block = WW/4 float4 groups

struct RowRegs {
    float4 v;   // 4 center values
    float  l;   // value at col-1 (replicated at left edge)
    float  r;   // value at col+4 (replicated at right edge)
};

__device__ __forceinline__ void load_row(const float* __restrict__ img,
                                         int y, int c, RowRegs& rr) {
    int yc = min(max(y, 0), HH - 1);
    const float* p = img + (size_t)yc * WW + c;
    rr.v = *reinterpret_cast<const float4*>(p);
    rr.l = (c > 0)        ? __ldg(p - 1) : rr.v.x;
    rr.r = (c + 4 < WW)   ? __ldg(p + 4) : rr.v.w;
}

// max of 3 horizontally adjacent values per lane (for rows above/below)
__device__ __forceinline__ float4 hmax3(const RowRegs& rr) {
    float4 h;
    h.x = fmaxf(fmaxf(rr.l,   rr.v.x), rr.v.y);
    h.y = fmaxf(fmaxf(rr.v.x, rr.v.y), rr.v.z);
    h.z = fmaxf(fmaxf(rr.v.y, rr.v.z), rr.v.w);
    h.w = fmaxf(fmaxf(rr.v.z, rr.v.w), rr.r);
    return h;
}

// max of the 2 horizontal neighbors (center excluded; for the center row)
__device__ __forceinline__ float4 hmax2(const RowRegs& rr) {
    float4 h;
    h.x = fmaxf(rr.l,   rr.v.y);
    h.y = fmaxf(rr.v.x, rr.v.z);
    h.z = fmaxf(rr.v.y, rr.v.w);
    h.w = fmaxf(rr.v.z, rr.r);
    return h;
}

__global__ __launch_bounds__(TPB)
void nms2d_kernel(const float* __restrict__ x, float* __restrict__ out) {
    const int tiles_per_img = HH / RPT;             // 32
    const int img  = blockIdx.x / tiles_per_img;
    const int tile = blockIdx.x % tiles_per_img;

    const float* in = x   + (size_t)img * HH * WW;
    float*       o  = out + (size_t)img * HH * WW;

    const int c  = threadIdx.x * 4;                 // 0..508
    const int y0 = tile * RPT;

    RowRegs prev, cur, next;
    load_row(in, y0 - 1, c, prev);
    load_row(in, y0,     c, cur);

    #pragma unroll
    for (int i = 0; i < RPT; i++) {
        const int y = y0 + i;
        load_row(in, y + 1, c, next);

        float4 mp = hmax3(prev);
        float4 mc = hmax2(cur);
        float4 mn = hmax3(next);

        float4 m;
        m.x = fmaxf(fmaxf(mp.x, mc.x), mn.x);
        m.y = fmaxf(fmaxf(mp.y, mc.y), mn.y);
        m.z = fmaxf(fmaxf(mp.z, mc.z), mn.z);
        m.w = fmaxf(fmaxf(mp.w, mc.w), mn.w);

        // reference inits running max at 0 (zeroed center tap), so the
        // effective threshold is max(m, 0): x must beat neighbors AND 0.
        float4 xc = cur.v;
        float4 r;
        r.x = (xc.x > m.x && xc.x > 0.0f) ? xc.x : 0.0f;
        r.y = (xc.y > m.y && xc.y > 0.0f) ? xc.y : 0.0f;
        r.z = (xc.z > m.z && xc.z > 0.0f) ? xc.z : 0.0f;
        r.w = (xc.w > m.w && xc.w > 0.0f) ? xc.w : 0.0f;

        *reinterpret_cast<float4*>(o + (size_t)y * WW + c) = r;

        prev = cur;
        cur  = next;
    }
}

extern "C" void kernel_launch(void* const* d_in, const int* in_sizes, int n_in,
                              void* d_out, int out_size) {
    const float* x = (const float*)d_in[0];
    float* out = (float*)d_out;

    const int n_img = in_sizes[0] / (HH * WW);      // B*C = 256
    const int blocks = n_img * (HH / RPT);          // 8192

    nms2d_kernel<<<blocks, TPB>>>(x, out);
}

// round 3
// speedup vs baseline: 1.0073x; 1.0073x over previous
#include <cuda_runtime.h>

// NonMaximaSuppression2d: x (8,32,512,512) fp32.
// m = max over 8 neighbors (replicate pad), floored at 0 (zeroed center tap).
// out = x * (x > m).
// HBM-streaming: float4 along W, 3-row register slide along H.
// R2 changes: RPT 16->32 (halo 1.125x->1.0625x), streaming stores (__stcs),
// folded zero-floor into the neighbor max (1 FMNMX instead of extra FSETP+LOP).

#define HH 512
#define WW 512
#define RPT 32          // rows per thread strip
#define TPB 128         // threads per block = WW/4 float4 groups

struct RowRegs {
    float4 v;   // 4 center values
    float  l;   // value at col-1 (replicated at left edge)
    float  r;   // value at col+4 (replicated at right edge)
};

__device__ __forceinline__ void load_row(const float* __restrict__ img,
                                         int y, int c, RowRegs& rr) {
    int yc = min(max(y, 0), HH - 1);
    const float* p = img + (size_t)yc * WW + c;
    rr.v = *reinterpret_cast<const float4*>(p);
    rr.l = (c > 0)      ? __ldg(p - 1) : rr.v.x;
    rr.r = (c + 4 < WW) ? __ldg(p + 4) : rr.v.w;
}

// max of 3 horizontally adjacent values per lane (rows above/below)
__device__ __forceinline__ float4 hmax3(const RowRegs& rr) {
    float4 h;
    h.x = fmaxf(fmaxf(rr.l,   rr.v.x), rr.v.y);
    h.y = fmaxf(fmaxf(rr.v.x, rr.v.y), rr.v.z);
    h.z = fmaxf(fmaxf(rr.v.y, rr.v.z), rr.v.w);
    h.w = fmaxf(fmaxf(rr.v.z, rr.v.w), rr.r);
    return h;
}

// max of the 2 horizontal neighbors (center excluded; for the center row)
__device__ __forceinline__ float4 hmax2(const RowRegs& rr) {
    float4 h;
    h.x = fmaxf(rr.l,   rr.v.y);
    h.y = fmaxf(rr.v.x, rr.v.z);
    h.z = fmaxf(rr.v.y, rr.v.w);
    h.w = fmaxf(rr.v.z, rr.r);
    return h;
}

__global__ __launch_bounds__(TPB)
void nms2d_kernel(const float* __restrict__ x, float* __restrict__ out) {
    const int tiles_per_img = HH / RPT;             // 16
    const int img  = blockIdx.x / tiles_per_img;
    const int tile = blockIdx.x % tiles_per_img;

    const float* in = x   + (size_t)img * HH * WW;
    float*       o  = out + (size_t)img * HH * WW;

    const int c  = threadIdx.x * 4;                 // 0..508
    const int y0 = tile * RPT;

    RowRegs prev, cur, next;
    load_row(in, y0 - 1, c, prev);
    load_row(in, y0,     c, cur);

    float* op = o + (size_t)y0 * WW + c;

    #pragma unroll
    for (int i = 0; i < RPT; i++) {
        load_row(in, y0 + i + 1, c, next);

        float4 mp = hmax3(prev);
        float4 mc = hmax2(cur);
        float4 mn = hmax3(next);

        // fold the zeroed-center-tap floor (max inits at 0 in the reference)
        float4 m;
        m.x = fmaxf(fmaxf(fmaxf(mp.x, mc.x), mn.x), 0.0f);
        m.y = fmaxf(fmaxf(fmaxf(mp.y, mc.y), mn.y), 0.0f);
        m.z = fmaxf(fmaxf(fmaxf(mp.z, mc.z), mn.z), 0.0f);
        m.w = fmaxf(fmaxf(fmaxf(mp.w, mc.w), mn.w), 0.0f);

        float4 xc = cur.v;
        float4 r;
        r.x = (xc.x > m.x) ? xc.x : 0.0f;
        r.y = (xc.y > m.y) ? xc.y : 0.0f;
        r.z = (xc.z > m.z) ? xc.z : 0.0f;
        r.w = (xc.w > m.w) ? xc.w : 0.0f;

        // streaming store: output is never re-read; don't pollute L2,
        // leave capacity for the inter-strip halo rows.
        __stcs(reinterpret_cast<float4*>(op), r);
        op += WW;

        prev = cur;
        cur  = next;
    }
}

extern "C" void kernel_launch(void* const* d_in, const int* in_sizes, int n_in,
                              void* d_out, int out_size) {
    const float* x = (const float*)d_in[0];
    float* out = (float*)d_out;

    const int n_img = in_sizes[0] / (HH * WW);      // B*C = 256
    const int blocks = n_img * (HH / RPT);          // 4096

    nms2d_kernel<<<blocks, TPB>>>(x, out);
}